// round 1
// baseline (speedup 1.0000x reference)
#include <cuda_runtime.h>

#define N_USERS 100000
#define N_ITEMS 200000
#define N_NODES (N_USERS + N_ITEMS)
#define DIM 64
#define VEC (DIM / 4)                 // 16 float4 per node row
#define NNZ 6400000
#define TOTAL_V4 (N_NODES * VEC)      // 4,800,000 float4 = 76.8 MB per buffer

// Ping-pong scratch buffers for layer embeddings (static device allocs only).
__device__ float4 g_buf0[TOTAL_V4];
__device__ float4 g_buf1[TOTAL_V4];

// buf0 = concat(user_emb, item_emb); acc (d_out) = buf0; buf1 = 0
__global__ void init_kernel(const float4* __restrict__ user,
                            const float4* __restrict__ item,
                            float4* __restrict__ acc) {
    int i = blockIdx.x * blockDim.x + threadIdx.x;
    if (i >= TOTAL_V4) return;
    const int uend = N_USERS * VEC;
    float4 v = (i < uend) ? user[i] : item[i - uend];
    g_buf0[i] = v;
    acc[i] = v;
    g_buf1[i] = make_float4(0.f, 0.f, 0.f, 0.f);
}

// Edge-parallel SpMM: y[rows[e]] += vals[e] * x[cols[e]]
// 16 threads per edge, one float4 (16B) each -> coalesced 256B gather + float4 RED.
// srcsel == 0: x = buf0, y = buf1;  srcsel == 1: x = buf1, y = buf0.
__global__ void spmm_kernel(const int* __restrict__ rows,
                            const int* __restrict__ cols,
                            const float* __restrict__ vals,
                            int srcsel) {
    long long t = (long long)blockIdx.x * blockDim.x + threadIdx.x;
    int e = (int)(t >> 4);
    if (e >= NNZ) return;
    int lane = (int)(t & 15);

    const float4* __restrict__ x = srcsel ? g_buf1 : g_buf0;
    float4* __restrict__ y       = srcsel ? g_buf0 : g_buf1;

    int r = rows[e];
    int c = cols[e];
    float v = vals[e];

    float4 xv = __ldg(&x[(long long)c * VEC + lane]);
    float4 a = make_float4(xv.x * v, xv.y * v, xv.z * v, xv.w * v);
    atomicAdd(&y[(long long)r * VEC + lane], a);   // sm_90+ vector atomic (RED.128)
}

// acc += (just-produced layer buffer); zero the other buffer for the next SpMM.
// srcsel == 1: src = buf1, zero buf0;  srcsel == 0: src = buf0, zero buf1.
__global__ void accum_zero_kernel(float4* __restrict__ acc, int srcsel) {
    int i = blockIdx.x * blockDim.x + threadIdx.x;
    if (i >= TOTAL_V4) return;
    const float4* __restrict__ src = srcsel ? g_buf1 : g_buf0;
    float4* __restrict__ tozero    = srcsel ? g_buf0 : g_buf1;
    float4 a = acc[i];
    float4 s = src[i];
    a.x += s.x; a.y += s.y; a.z += s.z; a.w += s.w;
    acc[i] = a;
    tozero[i] = make_float4(0.f, 0.f, 0.f, 0.f);
}

// acc = (acc + buf1) * 0.25  (final layer lives in buf1)
__global__ void final_kernel(float4* __restrict__ acc) {
    int i = blockIdx.x * blockDim.x + threadIdx.x;
    if (i >= TOTAL_V4) return;
    float4 a = acc[i];
    float4 s = g_buf1[i];
    a.x = (a.x + s.x) * 0.25f;
    a.y = (a.y + s.y) * 0.25f;
    a.z = (a.z + s.z) * 0.25f;
    a.w = (a.w + s.w) * 0.25f;
    acc[i] = a;
}

extern "C" void kernel_launch(void* const* d_in, const int* in_sizes, int n_in,
                              void* d_out, int out_size) {
    const float4* user = (const float4*)d_in[0];
    const float4* item = (const float4*)d_in[1];
    const int*   rows  = (const int*)d_in[2];
    const int*   cols  = (const int*)d_in[3];
    const float* vals  = (const float*)d_in[4];
    float4* acc = (float4*)d_out;

    const int BLK = 256;
    const int gridElem = (TOTAL_V4 + BLK - 1) / BLK;
    const long long spmmThreads = (long long)NNZ * 16;
    const int gridSpmm = (int)((spmmThreads + BLK - 1) / BLK);

    // x0: buf0 = concat embeddings, acc = x0, buf1 zeroed
    init_kernel<<<gridElem, BLK>>>(user, item, acc);

    // layer 1: x1 = A @ x0   (buf0 -> buf1)
    spmm_kernel<<<gridSpmm, BLK>>>(rows, cols, vals, 0);
    accum_zero_kernel<<<gridElem, BLK>>>(acc, 1);   // acc += x1, zero buf0

    // layer 2: x2 = A @ x1   (buf1 -> buf0)
    spmm_kernel<<<gridSpmm, BLK>>>(rows, cols, vals, 1);
    accum_zero_kernel<<<gridElem, BLK>>>(acc, 0);   // acc += x2, zero buf1

    // layer 3: x3 = A @ x2   (buf0 -> buf1)
    spmm_kernel<<<gridSpmm, BLK>>>(rows, cols, vals, 0);

    // acc = (acc + x3) / 4
    final_kernel<<<gridElem, BLK>>>(acc);
}

// round 2
// speedup vs baseline: 2.0199x; 2.0199x over previous
#include <cuda_runtime.h>

#define N_USERS 100000
#define N_ITEMS 200000
#define N_NODES (N_USERS + N_ITEMS)
#define DIM 64
#define NNZ 6400000
#define TOTAL_V2 (N_NODES * 32)      // float2 elements per buffer
#define SCAN_BLK 1024
#define N_SCAN_BLOCKS ((N_NODES + SCAN_BLK - 1) / SCAN_BLK)   // 293

// Static device scratch (no allocs allowed).
__device__ float2 g_buf0[TOTAL_V2];          // 76.8 MB
__device__ float2 g_buf1[TOTAL_V2];          // 76.8 MB
__device__ float2 g_cv[NNZ];                 // packed {col_bits, val}, 51.2 MB
__device__ int    g_rowptr[N_NODES + 1];
__device__ int    g_cursor[N_NODES];
__device__ int    g_deg[N_NODES];
__device__ int    g_bsum[SCAN_BLK];          // >= N_SCAN_BLOCKS

// ---------------- init: buf0 = concat(user,item); acc = buf0 ----------------
__global__ void init_kernel(const float2* __restrict__ user,
                            const float2* __restrict__ item,
                            float2* __restrict__ acc) {
    int i = blockIdx.x * blockDim.x + threadIdx.x;
    if (i >= TOTAL_V2) return;
    const int uend = N_USERS * 32;
    float2 v = (i < uend) ? user[i] : item[i - uend];
    g_buf0[i] = v;
    acc[i] = v;
}

// ---------------- CSR build: histogram -> scan -> scatter ----------------
__global__ void zero_deg_kernel() {
    int i = blockIdx.x * blockDim.x + threadIdx.x;
    if (i < N_NODES) g_deg[i] = 0;
}

__global__ void hist_kernel(const int* __restrict__ rows) {
    int e = blockIdx.x * blockDim.x + threadIdx.x;
    if (e < NNZ) atomicAdd(&g_deg[rows[e]], 1);
}

// per-block exclusive scan; block sums to g_bsum
__global__ void scan1_kernel() {
    __shared__ int s[SCAN_BLK];
    int t = threadIdx.x;
    int i = blockIdx.x * SCAN_BLK + t;
    int v = (i < N_NODES) ? g_deg[i] : 0;
    s[t] = v;
    __syncthreads();
    for (int off = 1; off < SCAN_BLK; off <<= 1) {
        int add = (t >= off) ? s[t - off] : 0;
        __syncthreads();
        s[t] += add;
        __syncthreads();
    }
    int incl = s[t];
    if (i < N_NODES) g_rowptr[i] = incl - v;          // exclusive within block
    if (t == SCAN_BLK - 1) g_bsum[blockIdx.x] = incl; // block total
}

// single-block exclusive scan of block sums (N_SCAN_BLOCKS=293 <= 512)
__global__ void scan2_kernel() {
    __shared__ int s[512];
    int t = threadIdx.x;
    int v = (t < N_SCAN_BLOCKS) ? g_bsum[t] : 0;
    s[t] = v;
    __syncthreads();
    for (int off = 1; off < 512; off <<= 1) {
        int add = (t >= off) ? s[t - off] : 0;
        __syncthreads();
        s[t] += add;
        __syncthreads();
    }
    if (t < N_SCAN_BLOCKS) g_bsum[t] = s[t] - v;      // exclusive block offsets
}

// add block offsets; cursor = rowptr; set sentinel
__global__ void scan3_kernel() {
    int i = blockIdx.x * blockDim.x + threadIdx.x;
    if (i >= N_NODES) return;
    int rp = g_rowptr[i] + g_bsum[i >> 10];
    g_rowptr[i] = rp;
    g_cursor[i] = rp;
    if (i == 0) g_rowptr[N_NODES] = NNZ;
}

__global__ void scatter_kernel(const int* __restrict__ rows,
                               const int* __restrict__ cols,
                               const float* __restrict__ vals) {
    int e = blockIdx.x * blockDim.x + threadIdx.x;
    if (e >= NNZ) return;
    int r = rows[e];
    int pos = atomicAdd(&g_cursor[r], 1);
    g_cv[pos] = make_float2(__int_as_float(cols[e]), vals[e]);
}

// ---------------- CSR SpMM: warp per row, register accumulator ----------------
// MODE 0: y[row] = sum; acc[row] += sum        (layers 1,2)
// MODE 1: acc[row] = (acc[row] + sum) * 0.25   (layer 3, no y store)
template <int MODE>
__global__ void spmm_csr_kernel(float2* __restrict__ acc, int srcsel) {
    int gtid = blockIdx.x * blockDim.x + threadIdx.x;
    int row = gtid >> 5;
    int lane = threadIdx.x & 31;
    if (row >= N_NODES) return;

    const float2* __restrict__ x = srcsel ? g_buf1 : g_buf0;
    float2* __restrict__ y       = srcsel ? g_buf0 : g_buf1;

    int start = g_rowptr[row];
    int end   = g_rowptr[row + 1];

    float2 sum = make_float2(0.f, 0.f);
    for (int k = start; k < end; k += 32) {
        int myk = k + lane;
        float2 cv = (myk < end) ? g_cv[myk] : make_float2(0.f, 0.f);
        int cnt = min(32, end - k);
        #pragma unroll 4
        for (int j = 0; j < cnt; j++) {
            int   cj = __shfl_sync(0xffffffffu, __float_as_int(cv.x), j);
            float vj = __shfl_sync(0xffffffffu, cv.y, j);
            float2 xv = __ldg(&x[cj * 32 + lane]);
            sum.x = fmaf(vj, xv.x, sum.x);
            sum.y = fmaf(vj, xv.y, sum.y);
        }
    }

    int oi = row * 32 + lane;
    float2 a = acc[oi];
    if (MODE == 0) {
        y[oi] = sum;
        a.x += sum.x; a.y += sum.y;
        acc[oi] = a;
    } else {
        a.x = (a.x + sum.x) * 0.25f;
        a.y = (a.y + sum.y) * 0.25f;
        acc[oi] = a;
    }
}

extern "C" void kernel_launch(void* const* d_in, const int* in_sizes, int n_in,
                              void* d_out, int out_size) {
    const float2* user = (const float2*)d_in[0];
    const float2* item = (const float2*)d_in[1];
    const int*   rows  = (const int*)d_in[2];
    const int*   cols  = (const int*)d_in[3];
    const float* vals  = (const float*)d_in[4];
    float2* acc = (float2*)d_out;

    const int BLK = 256;
    const int gridInit = (TOTAL_V2 + BLK - 1) / BLK;
    const int gridNode = (N_NODES + BLK - 1) / BLK;
    const int gridEdge = (NNZ + BLK - 1) / BLK;
    const int gridSpmm = (N_NODES * 32 + BLK - 1) / BLK;   // warp per row

    init_kernel<<<gridInit, BLK>>>(user, item, acc);

    // CSR build
    zero_deg_kernel<<<gridNode, BLK>>>();
    hist_kernel<<<gridEdge, BLK>>>(rows);
    scan1_kernel<<<N_SCAN_BLOCKS, SCAN_BLK>>>();
    scan2_kernel<<<1, 512>>>();
    scan3_kernel<<<gridNode, BLK>>>();
    scatter_kernel<<<gridEdge, BLK>>>(rows, cols, vals);

    // 3 propagation layers, accumulation fused
    spmm_csr_kernel<0><<<gridSpmm, BLK>>>(acc, 0);  // buf0 -> buf1, acc += x1
    spmm_csr_kernel<0><<<gridSpmm, BLK>>>(acc, 1);  // buf1 -> buf0, acc += x2
    spmm_csr_kernel<1><<<gridSpmm, BLK>>>(acc, 0);  // buf0 -> final: acc=(acc+x3)/4
}

// round 3
// speedup vs baseline: 2.5089x; 1.2421x over previous
#include <cuda_runtime.h>
#include <cuda_fp16.h>

#define N_USERS 100000
#define N_ITEMS 200000
#define N_NODES (N_USERS + N_ITEMS)
#define NNZ 6400000
#define H2_PER_NODE 32                      // 64 dims = 32 half2
#define BUF_H2 (N_NODES * H2_PER_NODE)      // 9.6M half2 = 38.4 MB
#define SCAN_BLK 1024
#define N_SCAN_BLOCKS ((N_NODES + SCAN_BLK - 1) / SCAN_BLK)   // 293

// Static device scratch. g_x[0]=x0, [1]=x1, [2]=x2, [3]=x3 (fp16).
__device__ __half2 g_x[4][BUF_H2];           // 4 x 38.4 MB
__device__ float2  g_cv[NNZ];                // packed {col_bits, val}
__device__ int     g_rowptr[N_NODES + 1];
__device__ int     g_cursor[N_NODES];
__device__ int     g_deg[N_NODES];
__device__ int     g_bsum[SCAN_BLK];

// ---------------- init: g_x[0] = fp16(concat(user,item)) ----------------
__global__ void init_kernel(const float2* __restrict__ user,
                            const float2* __restrict__ item) {
    int i = blockIdx.x * blockDim.x + threadIdx.x;
    if (i >= BUF_H2) return;
    const int uend = N_USERS * H2_PER_NODE;
    float2 v = (i < uend) ? user[i] : item[i - uend];
    g_x[0][i] = __float22half2_rn(v);
}

// ---------------- CSR build ----------------
__global__ void zero_deg_kernel() {
    int i = blockIdx.x * blockDim.x + threadIdx.x;
    if (i < N_NODES) g_deg[i] = 0;
}

__global__ void hist_kernel(const int* __restrict__ rows) {
    int e = blockIdx.x * blockDim.x + threadIdx.x;
    if (e < NNZ) atomicAdd(&g_deg[rows[e]], 1);
}

__global__ void scan1_kernel() {
    __shared__ int s[SCAN_BLK];
    int t = threadIdx.x;
    int i = blockIdx.x * SCAN_BLK + t;
    int v = (i < N_NODES) ? g_deg[i] : 0;
    s[t] = v;
    __syncthreads();
    for (int off = 1; off < SCAN_BLK; off <<= 1) {
        int add = (t >= off) ? s[t - off] : 0;
        __syncthreads();
        s[t] += add;
        __syncthreads();
    }
    int incl = s[t];
    if (i < N_NODES) g_rowptr[i] = incl - v;
    if (t == SCAN_BLK - 1) g_bsum[blockIdx.x] = incl;
}

__global__ void scan2_kernel() {
    __shared__ int s[512];
    int t = threadIdx.x;
    int v = (t < N_SCAN_BLOCKS) ? g_bsum[t] : 0;
    s[t] = v;
    __syncthreads();
    for (int off = 1; off < 512; off <<= 1) {
        int add = (t >= off) ? s[t - off] : 0;
        __syncthreads();
        s[t] += add;
        __syncthreads();
    }
    if (t < N_SCAN_BLOCKS) g_bsum[t] = s[t] - v;
}

__global__ void scan3_kernel() {
    int i = blockIdx.x * blockDim.x + threadIdx.x;
    if (i >= N_NODES) return;
    int rp = g_rowptr[i] + g_bsum[i >> 10];
    g_rowptr[i] = rp;
    g_cursor[i] = rp;
    if (i == 0) g_rowptr[N_NODES] = NNZ;
}

__global__ void scatter_kernel(const int* __restrict__ rows,
                               const int* __restrict__ cols,
                               const float* __restrict__ vals) {
    int e = blockIdx.x * blockDim.x + threadIdx.x;
    if (e >= NNZ) return;
    int r = rows[e];
    int pos = atomicAdd(&g_cursor[r], 1);
    g_cv[pos] = make_float2(__int_as_float(cols[e]), vals[e]);
}

// ---------------- CSR SpMM: warp per row, fp16 buffers, fp32 accum ----------------
__global__ void spmm_csr_kernel(int srcsel, int dstsel) {
    int gtid = blockIdx.x * blockDim.x + threadIdx.x;
    int row = gtid >> 5;
    int lane = threadIdx.x & 31;
    if (row >= N_NODES) return;

    const __half2* __restrict__ x = g_x[srcsel];
    __half2* __restrict__ y       = g_x[dstsel];

    int start = g_rowptr[row];
    int end   = g_rowptr[row + 1];

    float2 sum = make_float2(0.f, 0.f);
    for (int k = start; k < end; k += 32) {
        int myk = k + lane;
        float2 cv = (myk < end) ? g_cv[myk] : make_float2(0.f, 0.f);
        int cnt = min(32, end - k);
        #pragma unroll 4
        for (int j = 0; j < cnt; j++) {
            int   cj = __shfl_sync(0xffffffffu, __float_as_int(cv.x), j);
            float vj = __shfl_sync(0xffffffffu, cv.y, j);
            float2 xf = __half22float2(__ldg(&x[cj * H2_PER_NODE + lane]));
            sum.x = fmaf(vj, xf.x, sum.x);
            sum.y = fmaf(vj, xf.y, sum.y);
        }
    }
    y[row * H2_PER_NODE + lane] = __float22half2_rn(sum);
}

// ---------------- final: out = (x0_fp32 + x1 + x2 + x3) / 4 ----------------
__global__ void final_kernel(const float2* __restrict__ user,
                             const float2* __restrict__ item,
                             float2* __restrict__ out) {
    int i = blockIdx.x * blockDim.x + threadIdx.x;
    if (i >= BUF_H2) return;
    const int uend = N_USERS * H2_PER_NODE;
    float2 a = (i < uend) ? user[i] : item[i - uend];
    float2 x1 = __half22float2(g_x[1][i]);
    float2 x2 = __half22float2(g_x[2][i]);
    float2 x3 = __half22float2(g_x[3][i]);
    a.x = (a.x + x1.x + x2.x + x3.x) * 0.25f;
    a.y = (a.y + x1.y + x2.y + x3.y) * 0.25f;
    out[i] = a;
}

extern "C" void kernel_launch(void* const* d_in, const int* in_sizes, int n_in,
                              void* d_out, int out_size) {
    const float2* user = (const float2*)d_in[0];
    const float2* item = (const float2*)d_in[1];
    const int*   rows  = (const int*)d_in[2];
    const int*   cols  = (const int*)d_in[3];
    const float* vals  = (const float*)d_in[4];
    float2* out = (float2*)d_out;

    const int BLK = 256;
    const int gridBuf  = (BUF_H2 + BLK - 1) / BLK;
    const int gridNode = (N_NODES + BLK - 1) / BLK;
    const int gridEdge = (NNZ + BLK - 1) / BLK;
    const int gridSpmm = (N_NODES * 32 + BLK - 1) / BLK;   // warp per row

    init_kernel<<<gridBuf, BLK>>>(user, item);

    // CSR build
    zero_deg_kernel<<<gridNode, BLK>>>();
    hist_kernel<<<gridEdge, BLK>>>(rows);
    scan1_kernel<<<N_SCAN_BLOCKS, SCAN_BLK>>>();
    scan2_kernel<<<1, 512>>>();
    scan3_kernel<<<gridNode, BLK>>>();
    scatter_kernel<<<gridEdge, BLK>>>(rows, cols, vals);

    // 3 propagation layers (write-only outputs, no acc RMW)
    spmm_csr_kernel<<<gridSpmm, BLK>>>(0, 1);   // x1 = A @ x0
    spmm_csr_kernel<<<gridSpmm, BLK>>>(1, 2);   // x2 = A @ x1
    spmm_csr_kernel<<<gridSpmm, BLK>>>(2, 3);   // x3 = A @ x2

    final_kernel<<<gridBuf, BLK>>>(user, item, out);
}